// round 8
// baseline (speedup 1.0000x reference)
#include <cuda_runtime.h>
#include <stdint.h>

// out[c] = FACTOR * sum_e eng[e] * scales[sp[c], sp[n]]
// pass1 (scatter): tmp[c*16 + sp[n]] += eng[e]
// pass2 (reduce):  out[c] = FACTOR * dot(scales[sp[c],:], tmp[c,:])
// R8: cp.async 2-stage per-thread smem prefetch in scatter to hide LDG latency
// without register pressure (R4/R5 showed regs capped/occupancy tradeoff fails).

#define FACTOR 0.125f  // 1/sqrt(64)
#define TPB 512

__device__ uint32_t g_packed_species[32768];   // nibble-packed species (<=262144 nodes)
__device__ float    g_tmp[262144 * 16];        // (node, neighbor-species) accumulators

__global__ void pack_kernel(const int* __restrict__ species, int N, int nwords) {
    int i = blockIdx.x * blockDim.x + threadIdx.x;
    if (i >= nwords) return;
    int base = i << 3;
    uint32_t w = 0;
    if (base + 8 <= N) {
        int4 a = *(const int4*)&species[base];
        int4 b = *(const int4*)&species[base + 4];
        w  = ((uint32_t)a.x & 0xFu)
           | (((uint32_t)a.y & 0xFu) << 4)
           | (((uint32_t)a.z & 0xFu) << 8)
           | (((uint32_t)a.w & 0xFu) << 12)
           | (((uint32_t)b.x & 0xFu) << 16)
           | (((uint32_t)b.y & 0xFu) << 20)
           | (((uint32_t)b.z & 0xFu) << 24)
           | (((uint32_t)b.w & 0xFu) << 28);
    } else {
        for (int k = 0; k < 8; k++) {
            int idx = base + k;
            if (idx < N) w |= ((uint32_t)species[idx] & 0xFu) << (k << 2);
        }
    }
    g_packed_species[i] = w;
}

__device__ __forceinline__ void cp16(uint32_t dst_smem, const void* src) {
    asm volatile("cp.async.cg.shared.global [%0], [%1], 16;"
                 :: "r"(dst_smem), "l"(src));
}
__device__ __forceinline__ void cp_commit() {
    asm volatile("cp.async.commit_group;");
}
__device__ __forceinline__ void cp_wait1() {
    asm volatile("cp.async.wait_group 1;" ::: "memory");
}

__global__ __launch_bounds__(TPB, 2) void edge_scatter_kernel(
    const float* __restrict__ edge_eng,     // [E]
    const int*   __restrict__ ei_center,    // [E]
    const int*   __restrict__ ei_neighbor,  // [E]
    int E, int nwords)
{
    extern __shared__ uint32_t smem[];
    uint32_t* s_pack = smem;                          // nwords words
    int pack_pad = (nwords + 3) & ~3;                 // align to 16B
    float4* s_eng = (float4*)&smem[pack_pad];         // [2][TPB]
    int4*   s_ctr = (int4*)(s_eng + 2 * TPB);         // [2][TPB]
    int4*   s_nbr = (int4*)(s_ctr + 2 * TPB);         // [2][TPB]

    for (int i = threadIdx.x; i < nwords; i += blockDim.x)
        s_pack[i] = g_packed_species[i];
    __syncthreads();

    #define SPEC(idx) ((s_pack[(idx) >> 3] >> (((idx) & 7) << 2)) & 0xFu)

    int nvec = E >> 2;
    int t = threadIdx.x;
    int v0 = blockIdx.x * blockDim.x + t;
    int stride = gridDim.x * blockDim.x;

    const float4* eng4 = (const float4*)edge_eng;
    const int4*   c4   = (const int4*)ei_center;
    const int4*   n4   = (const int4*)ei_neighbor;

    uint32_t a_eng[2], a_ctr[2], a_nbr[2];
    #pragma unroll
    for (int s = 0; s < 2; s++) {
        a_eng[s] = (uint32_t)__cvta_generic_to_shared(&s_eng[s * TPB + t]);
        a_ctr[s] = (uint32_t)__cvta_generic_to_shared(&s_ctr[s * TPB + t]);
        a_nbr[s] = (uint32_t)__cvta_generic_to_shared(&s_nbr[s * TPB + t]);
    }

    // Prologue: prefetch 2 stages.
    #pragma unroll
    for (int s = 0; s < 2; s++) {
        int v = v0 + s * stride;
        if (v < nvec) {
            cp16(a_eng[s], eng4 + v);
            cp16(a_ctr[s], c4 + v);
            cp16(a_nbr[s], n4 + v);
        }
        cp_commit();
    }

    int iter = 0;
    for (int v = v0; v < nvec; v += stride, iter++) {
        cp_wait1();                    // our stage's group is complete
        int s = iter & 1;
        float4 e = s_eng[s * TPB + t];
        int4   c = s_ctr[s * TPB + t];
        int4   n = s_nbr[s * TPB + t];

        atomicAdd(&g_tmp[(c.x << 4) | SPEC(n.x)], e.x);
        atomicAdd(&g_tmp[(c.y << 4) | SPEC(n.y)], e.y);
        atomicAdd(&g_tmp[(c.z << 4) | SPEC(n.z)], e.z);
        atomicAdd(&g_tmp[(c.w << 4) | SPEC(n.w)], e.w);

        // Refill this slot for iteration iter+2 (after consumption).
        int vn = v + 2 * stride;
        if (vn < nvec) {
            cp16(a_eng[s], eng4 + vn);
            cp16(a_ctr[s], c4 + vn);
            cp16(a_nbr[s], n4 + vn);
        }
        cp_commit();
    }

    // Scalar tail (E not divisible by 4)
    int base = nvec << 2;
    for (int i = base + v0; i < E; i += stride) {
        int cc = ei_center[i];
        int nn = ei_neighbor[i];
        atomicAdd(&g_tmp[(cc << 4) | SPEC(nn)], edge_eng[i]);
    }
    #undef SPEC
}

__global__ __launch_bounds__(256) void node_reduce_kernel(
    const float* __restrict__ scales,   // [256]
    const int*   __restrict__ species,  // [N]
    float* __restrict__ out,            // [N]
    int N)
{
    __shared__ float s_scale[256];
    if (threadIdx.x < 256) s_scale[threadIdx.x] = scales[threadIdx.x];
    __syncthreads();

    int i = blockIdx.x * blockDim.x + threadIdx.x;
    if (i >= N) return;

    int sc = species[i] & 0xF;
    const float* srow = &s_scale[sc << 4];
    const float4* tp = (const float4*)&g_tmp[i << 4];

    float4 t0 = tp[0], t1 = tp[1], t2 = tp[2], t3 = tp[3];
    float acc = 0.0f;
    acc += t0.x * srow[0]  + t0.y * srow[1]  + t0.z * srow[2]  + t0.w * srow[3];
    acc += t1.x * srow[4]  + t1.y * srow[5]  + t1.z * srow[6]  + t1.w * srow[7];
    acc += t2.x * srow[8]  + t2.y * srow[9]  + t2.z * srow[10] + t2.w * srow[11];
    acc += t3.x * srow[12] + t3.y * srow[13] + t3.z * srow[14] + t3.w * srow[15];
    out[i] = acc * FACTOR;
}

extern "C" void kernel_launch(void* const* d_in, const int* in_sizes, int n_in,
                              void* d_out, int out_size) {
    const float* edge_eng = (const float*)d_in[0];  // [E,1]
    const float* scales   = (const float*)d_in[1];  // [16,16]
    const int*   edge_idx = (const int*)d_in[2];    // [2,E]
    const int*   species  = (const int*)d_in[3];    // [N]
    float* out = (float*)d_out;

    int E = in_sizes[0];
    int N = out_size;
    int nwords = (N + 7) >> 3;

    const int* ei_center   = edge_idx;
    const int* ei_neighbor = edge_idx + E;

    void* tmp_ptr = nullptr;
    cudaGetSymbolAddress(&tmp_ptr, g_tmp);
    cudaMemsetAsync(tmp_ptr, 0, (size_t)N * 16 * sizeof(float), 0);

    pack_kernel<<<(nwords + 255) / 256, 256>>>(species, N, nwords);

    int pack_pad = (nwords + 3) & ~3;
    size_t smem_bytes = (size_t)pack_pad * 4 + 2 * TPB * 48;  // pack + 2-stage buffers
    cudaFuncSetAttribute(edge_scatter_kernel,
                         cudaFuncAttributeMaxDynamicSharedMemorySize,
                         (int)smem_bytes);

    int nvec = E >> 2;
    int blocks = 148 * 2;
    int need = (nvec + TPB - 1) / TPB;
    if (blocks > need) blocks = need > 0 ? need : 1;
    edge_scatter_kernel<<<blocks, TPB, smem_bytes>>>(
        edge_eng, ei_center, ei_neighbor, E, nwords);

    node_reduce_kernel<<<(N + 255) / 256, 256>>>(scales, species, out, N);
}

// round 9
// speedup vs baseline: 1.1286x; 1.1286x over previous
#include <cuda_runtime.h>
#include <stdint.h>

// out[c] = FACTOR * sum_e eng[e] * scales[sp[c], sp[n]]
// pass0 (prep):   zero tmp (vectorized) + pack species nibbles   [fused]
// pass1 (scatter): tmp[c*16 + sp[n]] += eng[e]    (1 LDS + 1 RED per edge)
// pass2 (reduce):  out[c] = FACTOR * dot(scales[sp[c],:], tmp[c,:])
// Scatter sits on the L1tex-wavefront floor (~2cyc per scattered RED lane);
// R9 removes prep overhead (memset+pack fused, vectorized).

#define FACTOR 0.125f  // 1/sqrt(64)

__device__ uint32_t g_packed_species[32768];   // nibble-packed species (<=262144 nodes)
__device__ float    g_tmp[262144 * 16];        // (node, neighbor-species) accumulators

// Fused prep: zero tmp with float4 stores; first nwords threads also pack nibbles.
__global__ __launch_bounds__(256) void prep_kernel(
    const int* __restrict__ species, int N, int nwords, int ntmp4)
{
    int i = blockIdx.x * blockDim.x + threadIdx.x;
    if (i < ntmp4) ((float4*)g_tmp)[i] = make_float4(0.f, 0.f, 0.f, 0.f);
    if (i < nwords) {
        int base = i << 3;
        uint32_t w = 0;
        if (base + 8 <= N) {
            int4 a = *(const int4*)&species[base];
            int4 b = *(const int4*)&species[base + 4];
            w  = ((uint32_t)a.x & 0xFu)
               | (((uint32_t)a.y & 0xFu) << 4)
               | (((uint32_t)a.z & 0xFu) << 8)
               | (((uint32_t)a.w & 0xFu) << 12)
               | (((uint32_t)b.x & 0xFu) << 16)
               | (((uint32_t)b.y & 0xFu) << 20)
               | (((uint32_t)b.z & 0xFu) << 24)
               | (((uint32_t)b.w & 0xFu) << 28);
        } else {
            for (int k = 0; k < 8; k++) {
                int idx = base + k;
                if (idx < N) w |= ((uint32_t)species[idx] & 0xFu) << (k << 2);
            }
        }
        g_packed_species[i] = w;
    }
}

// Pass 1: scatter edge energies into (center, neighbor-species) bins.
__global__ __launch_bounds__(512) void edge_scatter_kernel(
    const float* __restrict__ edge_eng,     // [E]
    const int*   __restrict__ ei_center,    // [E]
    const int*   __restrict__ ei_neighbor,  // [E]
    int E, int nwords)
{
    extern __shared__ uint32_t s_pack[];    // nwords words (~50KB)
    for (int i = threadIdx.x; i < nwords; i += blockDim.x)
        s_pack[i] = g_packed_species[i];
    __syncthreads();

    #define SPEC(idx) ((s_pack[(idx) >> 3] >> (((idx) & 7) << 2)) & 0xFu)

    int nvec = E >> 2;
    int tid = blockIdx.x * blockDim.x + threadIdx.x;
    int stride = gridDim.x * blockDim.x;

    const float4* eng4 = (const float4*)edge_eng;
    const int4*   c4   = (const int4*)ei_center;
    const int4*   n4   = (const int4*)ei_neighbor;

    for (int v = tid; v < nvec; v += stride) {
        float4 e = __ldcs(&eng4[v]);
        int4   c = __ldcs(&c4[v]);
        int4   n = __ldcs(&n4[v]);
        atomicAdd(&g_tmp[(c.x << 4) | SPEC(n.x)], e.x);
        atomicAdd(&g_tmp[(c.y << 4) | SPEC(n.y)], e.y);
        atomicAdd(&g_tmp[(c.z << 4) | SPEC(n.z)], e.z);
        atomicAdd(&g_tmp[(c.w << 4) | SPEC(n.w)], e.w);
    }

    int base = nvec << 2;
    for (int i = base + tid; i < E; i += stride) {
        int cc = ei_center[i];
        int nn = ei_neighbor[i];
        atomicAdd(&g_tmp[(cc << 4) | SPEC(nn)], edge_eng[i]);
    }
    #undef SPEC
}

// Pass 2: per-node dot product with the species-pair scale row.
__global__ __launch_bounds__(256) void node_reduce_kernel(
    const float* __restrict__ scales,   // [256]
    const int*   __restrict__ species,  // [N]
    float* __restrict__ out,            // [N]
    int N)
{
    __shared__ float s_scale[256];
    if (threadIdx.x < 256) s_scale[threadIdx.x] = scales[threadIdx.x];
    __syncthreads();

    int i = blockIdx.x * blockDim.x + threadIdx.x;
    if (i >= N) return;

    int sc = species[i] & 0xF;
    const float* srow = &s_scale[sc << 4];
    const float4* tp = (const float4*)&g_tmp[i << 4];

    float4 t0 = tp[0], t1 = tp[1], t2 = tp[2], t3 = tp[3];
    float acc = 0.0f;
    acc += t0.x * srow[0]  + t0.y * srow[1]  + t0.z * srow[2]  + t0.w * srow[3];
    acc += t1.x * srow[4]  + t1.y * srow[5]  + t1.z * srow[6]  + t1.w * srow[7];
    acc += t2.x * srow[8]  + t2.y * srow[9]  + t2.z * srow[10] + t2.w * srow[11];
    acc += t3.x * srow[12] + t3.y * srow[13] + t3.z * srow[14] + t3.w * srow[15];
    out[i] = acc * FACTOR;
}

extern "C" void kernel_launch(void* const* d_in, const int* in_sizes, int n_in,
                              void* d_out, int out_size) {
    const float* edge_eng = (const float*)d_in[0];  // [E,1]
    const float* scales   = (const float*)d_in[1];  // [16,16]
    const int*   edge_idx = (const int*)d_in[2];    // [2,E]
    const int*   species  = (const int*)d_in[3];    // [N]
    float* out = (float*)d_out;

    int E = in_sizes[0];
    int N = out_size;
    int nwords = (N + 7) >> 3;
    int ntmp4 = (N << 4) >> 2;   // N*16 floats / 4 per float4

    const int* ei_center   = edge_idx;
    const int* ei_neighbor = edge_idx + E;

    int prep_n = (ntmp4 > nwords ? ntmp4 : nwords);
    prep_kernel<<<(prep_n + 255) / 256, 256>>>(species, N, nwords, ntmp4);

    size_t smem_bytes = (size_t)nwords * sizeof(uint32_t);
    cudaFuncSetAttribute(edge_scatter_kernel,
                         cudaFuncAttributeMaxDynamicSharedMemorySize,
                         (int)smem_bytes);

    int threads = 512;
    int blocks = 148 * 4;
    int nvec = E >> 2;
    int need = (nvec + threads - 1) / threads;
    if (blocks > need) blocks = need > 0 ? need : 1;
    edge_scatter_kernel<<<blocks, threads, smem_bytes>>>(
        edge_eng, ei_center, ei_neighbor, E, nwords);

    node_reduce_kernel<<<(N + 255) / 256, 256>>>(scales, species, out, N);
}